// round 5
// baseline (speedup 1.0000x reference)
#include <cuda_runtime.h>
#include <cuda_bf16.h>
#include <cstdint>
#include <math.h>

// ---------------- problem constants ----------------
constexpr int Bdim = 4;
constexpr int Tdim = 96;
constexpr int Ndim = 512;
constexpr int Hdim = 128;
constexpr int Mrows = Bdim * Tdim * Ndim;   // 196608

// scratch (allocation-free rule)
__device__ float g_expanded[(size_t)Mrows * 2 * Hdim];     // [M, 256] fp32
__device__ __nv_bfloat16 g_gHi[(size_t)Mrows * Hdim];      // gated hi plane
__device__ __nv_bfloat16 g_gLo[(size_t)Mrows * Hdim];      // gated lo plane
__device__ __nv_bfloat16 g_weHi[256 * 128];                // W_exp hi
__device__ __nv_bfloat16 g_weLo[256 * 128];                // W_exp lo
__device__ __nv_bfloat16 g_wcHi[128 * 128];                // W_con hi
__device__ __nv_bfloat16 g_wcLo[128 * 128];                // W_con lo

// ---------------- helpers ----------------
__device__ __forceinline__ uint32_t smem_u32(const void* p) {
    uint32_t a;
    asm("{ .reg .u64 t; cvta.to.shared.u64 t, %1; cvt.u32.u64 %0, t; }"
        : "=r"(a) : "l"(p));
    return a;
}

#define LDSM4(r, addr)                                                        \
    asm volatile("ldmatrix.sync.aligned.m8n8.x4.shared.b16 {%0,%1,%2,%3}, [%4];" \
                 : "=r"((r)[0]), "=r"((r)[1]), "=r"((r)[2]), "=r"((r)[3])     \
                 : "r"(addr))

#define MMA16816(d, a, b0, b1)                                                \
    asm volatile("mma.sync.aligned.m16n8k16.row.col.f32.bf16.bf16.f32 "       \
                 "{%0,%1,%2,%3}, {%4,%5,%6,%7}, {%8,%9}, {%0,%1,%2,%3};"      \
                 : "+f"((d)[0]), "+f"((d)[1]), "+f"((d)[2]), "+f"((d)[3])     \
                 : "r"((a)[0]), "r"((a)[1]), "r"((a)[2]), "r"((a)[3]),        \
                   "r"(b0), "r"(b1))

constexpr int LDS_STRIDE = 136;  // 128 + 8 bf16 pad (16B) -> conflict-free ldmatrix

// fp32 [128,128] row-major tile -> (hi, lo) bf16 smem tiles (stride 136)
template <int NTHREADS>
__device__ __forceinline__ void convert_tile(const float* __restrict__ src,
                                             __nv_bfloat16* __restrict__ hi,
                                             __nv_bfloat16* __restrict__ lo,
                                             int tid) {
#pragma unroll
    for (int it = 0; it < 4096 / NTHREADS; ++it) {
        int i  = tid + it * NTHREADS;  // float4 index, 4096 total
        int r  = i >> 5;
        int c4 = (i & 31) << 2;
        float4 v = *reinterpret_cast<const float4*>(src + (size_t)r * 128 + c4);

        __nv_bfloat162 h0 = __float22bfloat162_rn(make_float2(v.x, v.y));
        __nv_bfloat162 h1 = __float22bfloat162_rn(make_float2(v.z, v.w));
        float2 h0f = __bfloat1622float2(h0);
        float2 h1f = __bfloat1622float2(h1);
        __nv_bfloat162 l0 = __float22bfloat162_rn(make_float2(v.x - h0f.x, v.y - h0f.y));
        __nv_bfloat162 l1 = __float22bfloat162_rn(make_float2(v.z - h1f.x, v.w - h1f.y));

        int off = r * LDS_STRIDE + c4;
        uint2 hp, lp;
        hp.x = *reinterpret_cast<uint32_t*>(&h0);
        hp.y = *reinterpret_cast<uint32_t*>(&h1);
        lp.x = *reinterpret_cast<uint32_t*>(&l0);
        lp.y = *reinterpret_cast<uint32_t*>(&l1);
        *reinterpret_cast<uint2*>(hi + off) = hp;
        *reinterpret_cast<uint2*>(lo + off) = lp;
    }
}

// bf16 plane [ROWS,128] row-major -> smem tile (stride 136), uint4 copies
template <int ROWS, int NTHREADS>
__device__ __forceinline__ void copy_plane(const __nv_bfloat16* __restrict__ src,
                                           __nv_bfloat16* __restrict__ dst, int tid) {
    const uint4* s = reinterpret_cast<const uint4*>(src);
#pragma unroll
    for (int it = 0; it < (ROWS * 16) / NTHREADS; ++it) {
        int i = tid + it * NTHREADS;
        int r = i >> 4;
        int c = (i & 15) << 3;
        *reinterpret_cast<uint4*>(dst + r * LDS_STRIDE + c) = s[i];
    }
}

// ---------------- weight pre-split ----------------
__global__ __launch_bounds__(256)
void split_weights(const float* __restrict__ We, const float* __restrict__ Wc) {
    int i = blockIdx.x * blockDim.x + threadIdx.x;
    if (i < 256 * 128) {
        float w = We[i];
        __nv_bfloat16 h = __float2bfloat16_rn(w);
        g_weHi[i] = h;
        g_weLo[i] = __float2bfloat16_rn(w - __bfloat162float(h));
    }
    if (i < 128 * 128) {
        float w = Wc[i];
        __nv_bfloat16 h = __float2bfloat16_rn(w);
        g_wcHi[i] = h;
        g_wcLo[i] = __float2bfloat16_rn(w - __bfloat162float(h));
    }
}

// ---------------- GEMM1: expanded[M,256] = x[M,128] * W_exp^T + b ----------------
// One CTA per 128-row M-tile, full N=256. 16 warps, each 32x64.
__global__ __launch_bounds__(512, 1)
void gemm1(const float* __restrict__ A, const float* __restrict__ bias,
           float* __restrict__ C) {
    extern __shared__ char smem[];
    __nv_bfloat16* sAhi = reinterpret_cast<__nv_bfloat16*>(smem);
    __nv_bfloat16* sAlo = sAhi + 128 * LDS_STRIDE;
    __nv_bfloat16* sWhi = sAlo + 128 * LDS_STRIDE;
    __nv_bfloat16* sWlo = sWhi + 256 * LDS_STRIDE;

    const int tid  = threadIdx.x;
    const int wid  = tid >> 5;
    const int lane = tid & 31;
    const int bm0  = blockIdx.x * 128;

    convert_tile<512>(A + (size_t)bm0 * 128, sAhi, sAlo, tid);
    copy_plane<256, 512>(g_weHi, sWhi, tid);
    copy_plane<256, 512>(g_weLo, sWlo, tid);
    __syncthreads();

    const int m0 = (wid & 3) * 32;   // warp row offset
    const int n0 = (wid >> 2) * 64;  // warp col offset

    float acc[2][8][4];
#pragma unroll
    for (int i = 0; i < 2; ++i)
#pragma unroll
        for (int j = 0; j < 8; ++j)
#pragma unroll
            for (int q = 0; q < 4; ++q) acc[i][j][q] = 0.0f;

    uint32_t aHi[2], aLo[2], bHi[4], bLo[4];
    {
        const uint32_t aBaseHi = smem_u32(sAhi), aBaseLo = smem_u32(sAlo);
        const uint32_t bBaseHi = smem_u32(sWhi), bBaseLo = smem_u32(sWlo);
        int ar = m0 + (lane & 15);
        int ac = (lane >> 4) * 8;
#pragma unroll
        for (int i = 0; i < 2; ++i) {
            uint32_t off = ((ar + 16 * i) * LDS_STRIDE + ac) * 2;
            aHi[i] = aBaseHi + off;
            aLo[i] = aBaseLo + off;
        }
        int br = n0 + ((lane >> 4) << 3) + (lane & 7);
        int bc = ((lane >> 3) & 1) * 8;
#pragma unroll
        for (int j = 0; j < 4; ++j) {
            uint32_t off = ((br + 16 * j) * LDS_STRIDE + bc) * 2;
            bHi[j] = bBaseHi + off;
            bLo[j] = bBaseLo + off;
        }
    }

#pragma unroll 2
    for (int kk = 0; kk < 8; ++kk) {
        const uint32_t ko = kk * 32;
        uint32_t ah[2][4], al[2][4];
#pragma unroll
        for (int i = 0; i < 2; ++i) { LDSM4(ah[i], aHi[i] + ko); }
#pragma unroll
        for (int i = 0; i < 2; ++i) { LDSM4(al[i], aLo[i] + ko); }

#pragma unroll
        for (int nh = 0; nh < 2; ++nh) {
            uint32_t bh[2][4], bl[2][4];
            LDSM4(bh[0], bHi[nh * 2]     + ko);
            LDSM4(bh[1], bHi[nh * 2 + 1] + ko);
            LDSM4(bl[0], bLo[nh * 2]     + ko);
            LDSM4(bl[1], bLo[nh * 2 + 1] + ko);
#pragma unroll
            for (int i = 0; i < 2; ++i) {
#pragma unroll
                for (int jj = 0; jj < 4; ++jj) {
                    const int pr = jj >> 1, wh = (jj & 1) * 2;
                    float* d = acc[i][nh * 4 + jj];
                    MMA16816(d, ah[i], bh[pr][wh], bh[pr][wh + 1]);  // hi*hi
                    MMA16816(d, ah[i], bl[pr][wh], bl[pr][wh + 1]);  // hi*lo
                    MMA16816(d, al[i], bh[pr][wh], bh[pr][wh + 1]);  // lo*hi
                }
            }
        }
    }

    // epilogue: bias + float2 stores (C row length 256)
    const int gr = lane >> 2;
    const int gc = (lane & 3) * 2;
#pragma unroll
    for (int jj = 0; jj < 8; ++jj) {
        const int col = n0 + jj * 8 + gc;
        const float b0v = bias[col];
        const float b1v = bias[col + 1];
#pragma unroll
        for (int i = 0; i < 2; ++i) {
            const int row = bm0 + m0 + i * 16 + gr;
            float2 o0, o1;
            o0.x = acc[i][jj][0] + b0v; o0.y = acc[i][jj][1] + b1v;
            o1.x = acc[i][jj][2] + b0v; o1.y = acc[i][jj][3] + b1v;
            *reinterpret_cast<float2*>(&C[(size_t)row * 256 + col])       = o0;
            *reinterpret_cast<float2*>(&C[(size_t)(row + 8) * 256 + col]) = o1;
        }
    }
}

// ---------------- GEMM2: out[M,128] = gated[M,128] * W_con^T + b ----------------
// A arrives pre-split (bf16 hi/lo planes) — pure copy into smem, no conversion.
__global__ __launch_bounds__(512, 1)
void gemm2(const float* __restrict__ bias, float* __restrict__ C) {
    extern __shared__ char smem[];
    __nv_bfloat16* sAhi = reinterpret_cast<__nv_bfloat16*>(smem);
    __nv_bfloat16* sAlo = sAhi + 128 * LDS_STRIDE;
    __nv_bfloat16* sWhi = sAlo + 128 * LDS_STRIDE;
    __nv_bfloat16* sWlo = sWhi + 128 * LDS_STRIDE;

    const int tid  = threadIdx.x;
    const int wid  = tid >> 5;
    const int lane = tid & 31;
    const int bm0  = blockIdx.x * 128;

    copy_plane<128, 512>(g_gHi + (size_t)bm0 * 128, sAhi, tid);
    copy_plane<128, 512>(g_gLo + (size_t)bm0 * 128, sAlo, tid);
    copy_plane<128, 512>(g_wcHi, sWhi, tid);
    copy_plane<128, 512>(g_wcLo, sWlo, tid);
    __syncthreads();

    const int m0 = (wid & 3) * 32;
    const int n0 = (wid >> 2) * 32;

    float acc[2][4][4];
#pragma unroll
    for (int i = 0; i < 2; ++i)
#pragma unroll
        for (int j = 0; j < 4; ++j)
#pragma unroll
            for (int q = 0; q < 4; ++q) acc[i][j][q] = 0.0f;

    uint32_t aHi[2], aLo[2], bHi[2], bLo[2];
    {
        const uint32_t aBaseHi = smem_u32(sAhi), aBaseLo = smem_u32(sAlo);
        const uint32_t bBaseHi = smem_u32(sWhi), bBaseLo = smem_u32(sWlo);
        int ar = m0 + (lane & 15);
        int ac = (lane >> 4) * 8;
#pragma unroll
        for (int i = 0; i < 2; ++i) {
            uint32_t off = ((ar + 16 * i) * LDS_STRIDE + ac) * 2;
            aHi[i] = aBaseHi + off;
            aLo[i] = aBaseLo + off;
        }
        int br = n0 + ((lane >> 4) << 3) + (lane & 7);
        int bc = ((lane >> 3) & 1) * 8;
#pragma unroll
        for (int j = 0; j < 2; ++j) {
            uint32_t off = ((br + 16 * j) * LDS_STRIDE + bc) * 2;
            bHi[j] = bBaseHi + off;
            bLo[j] = bBaseLo + off;
        }
    }

#pragma unroll
    for (int kk = 0; kk < 8; ++kk) {
        const uint32_t ko = kk * 32;
        uint32_t ah[2][4], al[2][4], bh[2][4], bl[2][4];
#pragma unroll
        for (int i = 0; i < 2; ++i) { LDSM4(ah[i], aHi[i] + ko); }
#pragma unroll
        for (int j = 0; j < 2; ++j) { LDSM4(bh[j], bHi[j] + ko); }
#pragma unroll
        for (int i = 0; i < 2; ++i) { LDSM4(al[i], aLo[i] + ko); }
#pragma unroll
        for (int j = 0; j < 2; ++j) { LDSM4(bl[j], bLo[j] + ko); }

#pragma unroll
        for (int i = 0; i < 2; ++i) {
#pragma unroll
            for (int jj = 0; jj < 4; ++jj) {
                const int pr = jj >> 1, wh = (jj & 1) * 2;
                float* d = acc[i][jj];
                MMA16816(d, ah[i], bh[pr][wh], bh[pr][wh + 1]);
                MMA16816(d, ah[i], bl[pr][wh], bl[pr][wh + 1]);
                MMA16816(d, al[i], bh[pr][wh], bh[pr][wh + 1]);
            }
        }
    }

    const int gr = lane >> 2;
    const int gc = (lane & 3) * 2;
#pragma unroll
    for (int jj = 0; jj < 4; ++jj) {
        const int col = n0 + jj * 8 + gc;
        const float b0v = bias[col];
        const float b1v = bias[col + 1];
#pragma unroll
        for (int i = 0; i < 2; ++i) {
            const int row = bm0 + m0 + i * 16 + gr;
            float2 o0, o1;
            o0.x = acc[i][jj][0] + b0v; o0.y = acc[i][jj][1] + b1v;
            o1.x = acc[i][jj][2] + b0v; o1.y = acc[i][jj][3] + b1v;
            *reinterpret_cast<float2*>(&C[(size_t)row * 128 + col])       = o0;
            *reinterpret_cast<float2*>(&C[(size_t)(row + 8) * 128 + col]) = o1;
        }
    }
}

// ---------------- EMA scan + sigmoid gate; writes split-bf16 planes ----------------
__global__ __launch_bounds__(256)
void ema_gate_kernel(const float4* __restrict__ expanded) {
    int tid = blockIdx.x * blockDim.x + threadIdx.x;  // 0 .. B*N*32-1
    int h4 = tid & 31;
    int n  = (tid >> 5) & (Ndim - 1);
    int b  = tid >> 14;

    size_t base   = (((size_t)b * Tdim) * Ndim + n) * 64;   // expanded row = 64 f4
    size_t stride = (size_t)Ndim * 64;
    size_t ybase  = (((size_t)b * Tdim) * Ndim + n) * 32;   // plane row = 32 uint2
    size_t ystr   = (size_t)Ndim * 32;

    uint2* gHi = reinterpret_cast<uint2*>(g_gHi);
    uint2* gLo = reinterpret_cast<uint2*>(g_gLo);

    float4 s = make_float4(0.f, 0.f, 0.f, 0.f);
#pragma unroll 4
    for (int t = 0; t < Tdim; ++t) {
        float4 g = expanded[base + 32 + h4];
        float4 p = expanded[base + h4];
        s.x = fmaf(0.9f, s.x, 0.1f * g.x);
        s.y = fmaf(0.9f, s.y, 0.1f * g.y);
        s.z = fmaf(0.9f, s.z, 0.1f * g.z);
        s.w = fmaf(0.9f, s.w, 0.1f * g.w);
        float4 o;
        o.x = p.x / (1.0f + __expf(-s.x));
        o.y = p.y / (1.0f + __expf(-s.y));
        o.z = p.z / (1.0f + __expf(-s.z));
        o.w = p.w / (1.0f + __expf(-s.w));

        __nv_bfloat162 h0 = __float22bfloat162_rn(make_float2(o.x, o.y));
        __nv_bfloat162 h1 = __float22bfloat162_rn(make_float2(o.z, o.w));
        float2 h0f = __bfloat1622float2(h0);
        float2 h1f = __bfloat1622float2(h1);
        __nv_bfloat162 l0 = __float22bfloat162_rn(make_float2(o.x - h0f.x, o.y - h0f.y));
        __nv_bfloat162 l1 = __float22bfloat162_rn(make_float2(o.z - h1f.x, o.w - h1f.y));

        uint2 hp, lp;
        hp.x = *reinterpret_cast<uint32_t*>(&h0);
        hp.y = *reinterpret_cast<uint32_t*>(&h1);
        lp.x = *reinterpret_cast<uint32_t*>(&l0);
        lp.y = *reinterpret_cast<uint32_t*>(&l1);
        gHi[ybase + h4] = hp;
        gLo[ybase + h4] = lp;

        base  += stride;
        ybase += ystr;
    }
}

// ---------------- launch ----------------
extern "C" void kernel_launch(void* const* d_in, const int* in_sizes, int n_in,
                              void* d_out, int out_size) {
    const float* x     = (const float*)d_in[0];
    const float* W_exp = (const float*)d_in[1];
    const float* b_exp = (const float*)d_in[2];
    const float* W_con = (const float*)d_in[3];
    const float* b_con = (const float*)d_in[4];
    float* out = (float*)d_out;

    float* expanded;
    cudaGetSymbolAddress((void**)&expanded, g_expanded);

    constexpr int SMEM1 = (2 * 128 + 2 * 256) * LDS_STRIDE * 2;  // 208896
    constexpr int SMEM2 = 4 * 128 * LDS_STRIDE * 2;              // 139264
    cudaFuncSetAttribute(gemm1, cudaFuncAttributeMaxDynamicSharedMemorySize, SMEM1);
    cudaFuncSetAttribute(gemm2, cudaFuncAttributeMaxDynamicSharedMemorySize, SMEM2);

    split_weights<<<128, 256>>>(W_exp, W_con);

    gemm1<<<Mrows / 128, 512, SMEM1>>>(x, b_exp, expanded);

    ema_gate_kernel<<<(Bdim * Ndim * 32) / 256, 256>>>((const float4*)expanded);

    gemm2<<<Mrows / 128, 512, SMEM2>>>(b_con, out);
}

// round 6
// speedup vs baseline: 1.2079x; 1.2079x over previous
#include <cuda_runtime.h>
#include <cuda_bf16.h>
#include <cstdint>
#include <math.h>

// ---------------- problem constants ----------------
constexpr int Bdim = 4;
constexpr int Tdim = 96;
constexpr int Ndim = 512;
constexpr int Hdim = 128;
constexpr int Mrows = Bdim * Tdim * Ndim;   // 196608
constexpr int NTILES = Mrows / 64;          // 3072 tiles of 64 rows
constexpr int GRID_P = 148;                 // persistent grid (1 CTA/SM)

// scratch (allocation-free rule)
__device__ float g_expanded[(size_t)Mrows * 2 * Hdim];     // [M, 256] fp32
__device__ __nv_bfloat16 g_gHi[(size_t)Mrows * Hdim];      // gated hi plane
__device__ __nv_bfloat16 g_gLo[(size_t)Mrows * Hdim];      // gated lo plane
__device__ __nv_bfloat16 g_weHi[256 * 128];                // W_exp hi
__device__ __nv_bfloat16 g_weLo[256 * 128];                // W_exp lo
__device__ __nv_bfloat16 g_wcHi[128 * 128];                // W_con hi
__device__ __nv_bfloat16 g_wcLo[128 * 128];                // W_con lo

// ---------------- helpers ----------------
__device__ __forceinline__ uint32_t smem_u32(const void* p) {
    uint32_t a;
    asm("{ .reg .u64 t; cvta.to.shared.u64 t, %1; cvt.u32.u64 %0, t; }"
        : "=r"(a) : "l"(p));
    return a;
}

#define LDSM4(r, addr)                                                        \
    asm volatile("ldmatrix.sync.aligned.m8n8.x4.shared.b16 {%0,%1,%2,%3}, [%4];" \
                 : "=r"((r)[0]), "=r"((r)[1]), "=r"((r)[2]), "=r"((r)[3])     \
                 : "r"(addr))

#define MMA16816(d, a, b0, b1)                                                \
    asm volatile("mma.sync.aligned.m16n8k16.row.col.f32.bf16.bf16.f32 "       \
                 "{%0,%1,%2,%3}, {%4,%5,%6,%7}, {%8,%9}, {%0,%1,%2,%3};"      \
                 : "+f"((d)[0]), "+f"((d)[1]), "+f"((d)[2]), "+f"((d)[3])     \
                 : "r"((a)[0]), "r"((a)[1]), "r"((a)[2]), "r"((a)[3]),        \
                   "r"(b0), "r"(b1))

constexpr int LDS_STRIDE = 136;  // 128 + 8 bf16 pad -> conflict-free ldmatrix

// bf16 plane [ROWS,128] row-major -> smem tile (stride 136), uint4 copies
template <int ROWS, int NTHREADS>
__device__ __forceinline__ void copy_plane(const __nv_bfloat16* __restrict__ src,
                                           __nv_bfloat16* __restrict__ dst, int tid) {
    const uint4* s = reinterpret_cast<const uint4*>(src);
#pragma unroll
    for (int it = 0; it < (ROWS * 16) / NTHREADS; ++it) {
        int i = tid + it * NTHREADS;
        int r = i >> 4;
        int c = (i & 15) << 3;
        *reinterpret_cast<uint4*>(dst + r * LDS_STRIDE + c) = s[i];
    }
}

// ---------------- weight pre-split ----------------
__global__ __launch_bounds__(256)
void split_weights(const float* __restrict__ We, const float* __restrict__ Wc) {
    int i = blockIdx.x * blockDim.x + threadIdx.x;
    if (i < 256 * 128) {
        float w = We[i];
        __nv_bfloat16 h = __float2bfloat16_rn(w);
        g_weHi[i] = h;
        g_weLo[i] = __float2bfloat16_rn(w - __bfloat162float(h));
    }
    if (i < 128 * 128) {
        float w = Wc[i];
        __nv_bfloat16 h = __float2bfloat16_rn(w);
        g_wcHi[i] = h;
        g_wcLo[i] = __float2bfloat16_rn(w - __bfloat162float(h));
    }
}

// ---------------- GEMM1 (persistent): expanded[M,256] = x[M,128]*W_exp^T + b ----------------
// W_exp planes resident in smem; 64-row A tiles, register-prefetched one tile ahead.
__global__ __launch_bounds__(512, 1)
void gemm1_p(const float* __restrict__ A, const float* __restrict__ bias,
             float* __restrict__ C) {
    extern __shared__ char smem[];
    __nv_bfloat16* sWhi = reinterpret_cast<__nv_bfloat16*>(smem);          // 256 rows
    __nv_bfloat16* sWlo = sWhi + 256 * LDS_STRIDE;
    __nv_bfloat16* sAhi = sWlo + 256 * LDS_STRIDE;                         // 64 rows
    __nv_bfloat16* sAlo = sAhi + 64 * LDS_STRIDE;

    const int tid  = threadIdx.x;
    const int wid  = tid >> 5;
    const int lane = tid & 31;

    copy_plane<256, 512>(g_weHi, sWhi, tid);
    copy_plane<256, 512>(g_weLo, sWlo, tid);

    // warp layout: 2 (m) x 8 (n); each warp 32x32 of 64x256 tile
    const int m0 = (wid & 1) * 32;
    const int n0 = (wid >> 1) * 32;

    // ldmatrix addresses
    uint32_t aHiAd[2], aLoAd[2], bHiAd[2], bLoAd[2];
    {
        const uint32_t aBH = smem_u32(sAhi), aBL = smem_u32(sAlo);
        const uint32_t bBH = smem_u32(sWhi), bBL = smem_u32(sWlo);
        int ar = m0 + (lane & 15);
        int ac = (lane >> 4) * 8;
#pragma unroll
        for (int i = 0; i < 2; ++i) {
            uint32_t off = ((ar + 16 * i) * LDS_STRIDE + ac) * 2;
            aHiAd[i] = aBH + off;
            aLoAd[i] = aBL + off;
        }
        int br = n0 + ((lane >> 4) << 3) + (lane & 7);
        int bc = ((lane >> 3) & 1) * 8;
#pragma unroll
        for (int j = 0; j < 2; ++j) {
            uint32_t off = ((br + 16 * j) * LDS_STRIDE + bc) * 2;
            bHiAd[j] = bBH + off;
            bLoAd[j] = bBL + off;
        }
    }

    // prefetch tile0 (4 float4/thread covers 64x128 fp32)
    float4 pf[4];
    {
        int t0 = blockIdx.x;
        if (t0 < NTILES) {
#pragma unroll
            for (int it = 0; it < 4; ++it) {
                int i = tid + it * 512;
                int r = i >> 5, c4 = (i & 31) << 2;
                pf[it] = *reinterpret_cast<const float4*>(
                    A + ((size_t)t0 * 64 + r) * 128 + c4);
            }
        }
    }

    const int gr = lane >> 2;
    const int gc = (lane & 3) * 2;
    float bv[8][2];
#pragma unroll
    for (int jj = 0; jj < 8; ++jj) {
        // only first 4 jj used per warp? no: 4 col-blocks of 8 => jj<4; keep 4
        if (jj < 4) {
            bv[jj][0] = bias[n0 + jj * 8 + gc];
            bv[jj][1] = bias[n0 + jj * 8 + gc + 1];
        }
    }

    for (int tile = blockIdx.x; tile < NTILES; tile += GRID_P) {
        __syncthreads();  // previous MMAs done reading sA
        // convert prefetched fp32 -> split bf16 planes in smem
#pragma unroll
        for (int it = 0; it < 4; ++it) {
            int i = tid + it * 512;
            int r = i >> 5, c4 = (i & 31) << 2;
            float4 v = pf[it];
            __nv_bfloat162 h0 = __float22bfloat162_rn(make_float2(v.x, v.y));
            __nv_bfloat162 h1 = __float22bfloat162_rn(make_float2(v.z, v.w));
            float2 h0f = __bfloat1622float2(h0);
            float2 h1f = __bfloat1622float2(h1);
            __nv_bfloat162 l0 = __float22bfloat162_rn(make_float2(v.x - h0f.x, v.y - h0f.y));
            __nv_bfloat162 l1 = __float22bfloat162_rn(make_float2(v.z - h1f.x, v.w - h1f.y));
            int off = r * LDS_STRIDE + c4;
            uint2 hp, lp;
            hp.x = *reinterpret_cast<uint32_t*>(&h0);
            hp.y = *reinterpret_cast<uint32_t*>(&h1);
            lp.x = *reinterpret_cast<uint32_t*>(&l0);
            lp.y = *reinterpret_cast<uint32_t*>(&l1);
            *reinterpret_cast<uint2*>(sAhi + off) = hp;
            *reinterpret_cast<uint2*>(sAlo + off) = lp;
        }
        __syncthreads();

        // issue prefetch LDGs for next tile (hidden under MMA below)
        int next = tile + GRID_P;
        if (next < NTILES) {
#pragma unroll
            for (int it = 0; it < 4; ++it) {
                int i = tid + it * 512;
                int r = i >> 5, c4 = (i & 31) << 2;
                pf[it] = *reinterpret_cast<const float4*>(
                    A + ((size_t)next * 64 + r) * 128 + c4);
            }
        }

        float acc[2][4][4];
#pragma unroll
        for (int i = 0; i < 2; ++i)
#pragma unroll
            for (int j = 0; j < 4; ++j)
#pragma unroll
                for (int q = 0; q < 4; ++q) acc[i][j][q] = 0.0f;

#pragma unroll
        for (int kk = 0; kk < 8; ++kk) {
            const uint32_t ko = kk * 32;
            uint32_t ah[2][4], al[2][4], bh[2][4], bl[2][4];
#pragma unroll
            for (int i = 0; i < 2; ++i) { LDSM4(ah[i], aHiAd[i] + ko); }
#pragma unroll
            for (int j = 0; j < 2; ++j) { LDSM4(bh[j], bHiAd[j] + ko); }
#pragma unroll
            for (int i = 0; i < 2; ++i) { LDSM4(al[i], aLoAd[i] + ko); }
#pragma unroll
            for (int j = 0; j < 2; ++j) { LDSM4(bl[j], bLoAd[j] + ko); }
#pragma unroll
            for (int i = 0; i < 2; ++i) {
#pragma unroll
                for (int jj = 0; jj < 4; ++jj) {
                    const int pr = jj >> 1, wh = (jj & 1) * 2;
                    float* d = acc[i][jj];
                    MMA16816(d, ah[i], bh[pr][wh], bh[pr][wh + 1]);
                    MMA16816(d, ah[i], bl[pr][wh], bl[pr][wh + 1]);
                    MMA16816(d, al[i], bh[pr][wh], bh[pr][wh + 1]);
                }
            }
        }

        // epilogue
        const int bm0 = tile * 64;
#pragma unroll
        for (int jj = 0; jj < 4; ++jj) {
            const int col = n0 + jj * 8 + gc;
#pragma unroll
            for (int i = 0; i < 2; ++i) {
                const int row = bm0 + m0 + i * 16 + gr;
                float2 o0, o1;
                o0.x = acc[i][jj][0] + bv[jj][0]; o0.y = acc[i][jj][1] + bv[jj][1];
                o1.x = acc[i][jj][2] + bv[jj][0]; o1.y = acc[i][jj][3] + bv[jj][1];
                *reinterpret_cast<float2*>(&C[(size_t)row * 256 + col])       = o0;
                *reinterpret_cast<float2*>(&C[(size_t)(row + 8) * 256 + col]) = o1;
            }
        }
    }
}

// ---------------- GEMM2 (persistent): out[M,128] = gated[M,128]*W_con^T + b ----------------
// A arrives pre-split bf16 planes; prefetch next tile via registers.
__global__ __launch_bounds__(512, 1)
void gemm2_p(const float* __restrict__ bias, float* __restrict__ C) {
    extern __shared__ char smem[];
    __nv_bfloat16* sWhi = reinterpret_cast<__nv_bfloat16*>(smem);          // 128 rows
    __nv_bfloat16* sWlo = sWhi + 128 * LDS_STRIDE;
    __nv_bfloat16* sAhi = sWlo + 128 * LDS_STRIDE;                         // 64 rows
    __nv_bfloat16* sAlo = sAhi + 64 * LDS_STRIDE;

    const int tid  = threadIdx.x;
    const int wid  = tid >> 5;
    const int lane = tid & 31;

    copy_plane<128, 512>(g_wcHi, sWhi, tid);
    copy_plane<128, 512>(g_wcLo, sWlo, tid);

    // warp layout: 4 (m) x 4 (n); each warp 16x32 of 64x128 tile
    const int m0 = (wid & 3) * 16;
    const int n0 = (wid >> 2) * 32;

    uint32_t aHiAd, aLoAd, bHiAd[2], bLoAd[2];
    {
        const uint32_t aBH = smem_u32(sAhi), aBL = smem_u32(sAlo);
        const uint32_t bBH = smem_u32(sWhi), bBL = smem_u32(sWlo);
        int ar = m0 + (lane & 15);
        int ac = (lane >> 4) * 8;
        uint32_t off = (ar * LDS_STRIDE + ac) * 2;
        aHiAd = aBH + off;
        aLoAd = aBL + off;
        int br = n0 + ((lane >> 4) << 3) + (lane & 7);
        int bc = ((lane >> 3) & 1) * 8;
#pragma unroll
        for (int j = 0; j < 2; ++j) {
            uint32_t o2 = ((br + 16 * j) * LDS_STRIDE + bc) * 2;
            bHiAd[j] = bBH + o2;
            bLoAd[j] = bBL + o2;
        }
    }

    // prefetch tile0: hi plane 2 uint4/thread, lo plane 2 uint4/thread
    uint4 pfh[2], pfl[2];
    {
        int t0 = blockIdx.x;
        if (t0 < NTILES) {
            const uint4* sh = reinterpret_cast<const uint4*>(g_gHi + (size_t)t0 * 64 * 128);
            const uint4* sl = reinterpret_cast<const uint4*>(g_gLo + (size_t)t0 * 64 * 128);
#pragma unroll
            for (int it = 0; it < 2; ++it) {
                pfh[it] = sh[tid + it * 512];
                pfl[it] = sl[tid + it * 512];
            }
        }
    }

    const int gr = lane >> 2;
    const int gc = (lane & 3) * 2;
    float bv[4][2];
#pragma unroll
    for (int jj = 0; jj < 4; ++jj) {
        bv[jj][0] = bias[n0 + jj * 8 + gc];
        bv[jj][1] = bias[n0 + jj * 8 + gc + 1];
    }

    for (int tile = blockIdx.x; tile < NTILES; tile += GRID_P) {
        __syncthreads();
#pragma unroll
        for (int it = 0; it < 2; ++it) {
            int i = tid + it * 512;
            int r = i >> 4, c = (i & 15) << 3;
            *reinterpret_cast<uint4*>(sAhi + r * LDS_STRIDE + c) = pfh[it];
            *reinterpret_cast<uint4*>(sAlo + r * LDS_STRIDE + c) = pfl[it];
        }
        __syncthreads();

        int next = tile + GRID_P;
        if (next < NTILES) {
            const uint4* sh = reinterpret_cast<const uint4*>(g_gHi + (size_t)next * 64 * 128);
            const uint4* sl = reinterpret_cast<const uint4*>(g_gLo + (size_t)next * 64 * 128);
#pragma unroll
            for (int it = 0; it < 2; ++it) {
                pfh[it] = sh[tid + it * 512];
                pfl[it] = sl[tid + it * 512];
            }
        }

        float acc[4][4];
#pragma unroll
        for (int j = 0; j < 4; ++j)
#pragma unroll
            for (int q = 0; q < 4; ++q) acc[j][q] = 0.0f;

#pragma unroll
        for (int kk = 0; kk < 8; ++kk) {
            const uint32_t ko = kk * 32;
            uint32_t ah[4], al[4], bh[2][4], bl[2][4];
            LDSM4(ah, aHiAd + ko);
#pragma unroll
            for (int j = 0; j < 2; ++j) { LDSM4(bh[j], bHiAd[j] + ko); }
            LDSM4(al, aLoAd + ko);
#pragma unroll
            for (int j = 0; j < 2; ++j) { LDSM4(bl[j], bLoAd[j] + ko); }
#pragma unroll
            for (int jj = 0; jj < 4; ++jj) {
                const int pr = jj >> 1, wh = (jj & 1) * 2;
                float* d = acc[jj];
                MMA16816(d, ah, bh[pr][wh], bh[pr][wh + 1]);
                MMA16816(d, ah, bl[pr][wh], bl[pr][wh + 1]);
                MMA16816(d, al, bh[pr][wh], bh[pr][wh + 1]);
            }
        }

        const int bm0 = tile * 64;
#pragma unroll
        for (int jj = 0; jj < 4; ++jj) {
            const int col = n0 + jj * 8 + gc;
            const int row = bm0 + m0 + gr;
            float2 o0, o1;
            o0.x = acc[jj][0] + bv[jj][0]; o0.y = acc[jj][1] + bv[jj][1];
            o1.x = acc[jj][2] + bv[jj][0]; o1.y = acc[jj][3] + bv[jj][1];
            *reinterpret_cast<float2*>(&C[(size_t)row * 128 + col])       = o0;
            *reinterpret_cast<float2*>(&C[(size_t)(row + 8) * 128 + col]) = o1;
        }
    }
}

// ---------------- EMA scan + sigmoid gate; writes split-bf16 planes ----------------
__global__ __launch_bounds__(256)
void ema_gate_kernel(const float4* __restrict__ expanded) {
    int tid = blockIdx.x * blockDim.x + threadIdx.x;
    int h4 = tid & 31;
    int n  = (tid >> 5) & (Ndim - 1);
    int b  = tid >> 14;

    size_t base   = (((size_t)b * Tdim) * Ndim + n) * 64;
    size_t stride = (size_t)Ndim * 64;
    size_t ybase  = (((size_t)b * Tdim) * Ndim + n) * 32;
    size_t ystr   = (size_t)Ndim * 32;

    uint2* gHi = reinterpret_cast<uint2*>(g_gHi);
    uint2* gLo = reinterpret_cast<uint2*>(g_gLo);

    float4 s = make_float4(0.f, 0.f, 0.f, 0.f);
#pragma unroll 4
    for (int t = 0; t < Tdim; ++t) {
        float4 g = expanded[base + 32 + h4];
        float4 p = expanded[base + h4];
        s.x = fmaf(0.9f, s.x, 0.1f * g.x);
        s.y = fmaf(0.9f, s.y, 0.1f * g.y);
        s.z = fmaf(0.9f, s.z, 0.1f * g.z);
        s.w = fmaf(0.9f, s.w, 0.1f * g.w);
        float4 o;
        o.x = p.x / (1.0f + __expf(-s.x));
        o.y = p.y / (1.0f + __expf(-s.y));
        o.z = p.z / (1.0f + __expf(-s.z));
        o.w = p.w / (1.0f + __expf(-s.w));

        __nv_bfloat162 h0 = __float22bfloat162_rn(make_float2(o.x, o.y));
        __nv_bfloat162 h1 = __float22bfloat162_rn(make_float2(o.z, o.w));
        float2 h0f = __bfloat1622float2(h0);
        float2 h1f = __bfloat1622float2(h1);
        __nv_bfloat162 l0 = __float22bfloat162_rn(make_float2(o.x - h0f.x, o.y - h0f.y));
        __nv_bfloat162 l1 = __float22bfloat162_rn(make_float2(o.z - h1f.x, o.w - h1f.y));

        uint2 hp, lp;
        hp.x = *reinterpret_cast<uint32_t*>(&h0);
        hp.y = *reinterpret_cast<uint32_t*>(&h1);
        lp.x = *reinterpret_cast<uint32_t*>(&l0);
        lp.y = *reinterpret_cast<uint32_t*>(&l1);
        gHi[ybase + h4] = hp;
        gLo[ybase + h4] = lp;

        base  += stride;
        ybase += ystr;
    }
}

// ---------------- launch ----------------
extern "C" void kernel_launch(void* const* d_in, const int* in_sizes, int n_in,
                              void* d_out, int out_size) {
    const float* x     = (const float*)d_in[0];
    const float* W_exp = (const float*)d_in[1];
    const float* b_exp = (const float*)d_in[2];
    const float* W_con = (const float*)d_in[3];
    const float* b_con = (const float*)d_in[4];
    float* out = (float*)d_out;

    float* expanded;
    cudaGetSymbolAddress((void**)&expanded, g_expanded);

    constexpr int SMEM1 = (2 * 256 + 2 * 64) * LDS_STRIDE * 2;  // 174080
    constexpr int SMEM2 = (2 * 128 + 2 * 64) * LDS_STRIDE * 2;  // 104448
    cudaFuncSetAttribute(gemm1_p, cudaFuncAttributeMaxDynamicSharedMemorySize, SMEM1);
    cudaFuncSetAttribute(gemm2_p, cudaFuncAttributeMaxDynamicSharedMemorySize, SMEM2);

    split_weights<<<128, 256>>>(W_exp, W_con);

    gemm1_p<<<GRID_P, 512, SMEM1>>>(x, b_exp, expanded);

    ema_gate_kernel<<<(Bdim * Ndim * 32) / 256, 256>>>((const float4*)expanded);

    gemm2_p<<<GRID_P, 512, SMEM2>>>(b_con, out);
}

// round 7
// speedup vs baseline: 1.3515x; 1.1189x over previous
#include <cuda_runtime.h>
#include <cuda_bf16.h>
#include <cstdint>
#include <math.h>

// ---------------- problem constants ----------------
constexpr int Bdim = 4;
constexpr int Tdim = 96;
constexpr int Ndim = 512;
constexpr int Hdim = 128;
constexpr int Mrows = Bdim * Tdim * Ndim;   // 196608
constexpr int NT2   = Mrows / 128;          // 1536 tiles for gemm2
constexpr int GRID_P = 148;

// scratch (allocation-free rule)
__device__ __nv_bfloat16 g_gHi[(size_t)Mrows * Hdim];      // gated hi plane
__device__ __nv_bfloat16 g_gLo[(size_t)Mrows * Hdim];      // gated lo plane
__device__ __nv_bfloat16 g_weHi[256 * 128];                // W_exp hi
__device__ __nv_bfloat16 g_weLo[256 * 128];                // W_exp lo
__device__ __nv_bfloat16 g_wcHi[128 * 128];                // W_con hi
__device__ __nv_bfloat16 g_wcLo[128 * 128];                // W_con lo

// ---------------- helpers ----------------
__device__ __forceinline__ uint32_t smem_u32(const void* p) {
    uint32_t a;
    asm("{ .reg .u64 t; cvta.to.shared.u64 t, %1; cvt.u32.u64 %0, t; }"
        : "=r"(a) : "l"(p));
    return a;
}

#define LDSM4(r, addr)                                                        \
    asm volatile("ldmatrix.sync.aligned.m8n8.x4.shared.b16 {%0,%1,%2,%3}, [%4];" \
                 : "=r"((r)[0]), "=r"((r)[1]), "=r"((r)[2]), "=r"((r)[3])     \
                 : "r"(addr))

#define MMA16816(d, a, b0, b1)                                                \
    asm volatile("mma.sync.aligned.m16n8k16.row.col.f32.bf16.bf16.f32 "       \
                 "{%0,%1,%2,%3}, {%4,%5,%6,%7}, {%8,%9}, {%0,%1,%2,%3};"      \
                 : "+f"((d)[0]), "+f"((d)[1]), "+f"((d)[2]), "+f"((d)[3])     \
                 : "r"((a)[0]), "r"((a)[1]), "r"((a)[2]), "r"((a)[3]),        \
                   "r"(b0), "r"(b1))

constexpr int LDS_STRIDE = 136;  // 128 + 8 bf16 pad -> conflict-free smem

// bf16 plane [ROWS,128] row-major -> smem tile (stride 136), uint4 copies
template <int ROWS, int NTHREADS>
__device__ __forceinline__ void copy_plane(const __nv_bfloat16* __restrict__ src,
                                           __nv_bfloat16* __restrict__ dst, int tid) {
    const uint4* s = reinterpret_cast<const uint4*>(src);
#pragma unroll
    for (int it = 0; it < (ROWS * 16) / NTHREADS; ++it) {
        int i = tid + it * NTHREADS;
        int r = i >> 4;
        int c = (i & 15) << 3;
        *reinterpret_cast<uint4*>(dst + r * LDS_STRIDE + c) = s[i];
    }
}

// ---------------- weight pre-split ----------------
__global__ __launch_bounds__(256)
void split_weights(const float* __restrict__ We, const float* __restrict__ Wc) {
    int i = blockIdx.x * blockDim.x + threadIdx.x;
    if (i < 256 * 128) {
        float w = We[i];
        __nv_bfloat16 h = __float2bfloat16_rn(w);
        g_weHi[i] = h;
        g_weLo[i] = __float2bfloat16_rn(w - __bfloat162float(h));
    }
    if (i < 128 * 128) {
        float w = Wc[i];
        __nv_bfloat16 h = __float2bfloat16_rn(w);
        g_wcHi[i] = h;
        g_wcLo[i] = __float2bfloat16_rn(w - __bfloat162float(h));
    }
}

// ---------------- fused GEMM1 + EMA scan + gate ----------------
// Grid: 128 CTAs = (b in 0..3) x (n-chunk of 16, 32 chunks). Block: 256 (8 warps).
// CTA walks t = 0..95 sequentially; EMA state lives in registers.
// Warp w owns expanded cols: primary [16w,16w+16) and gating [128+16w, 128+16w+16).
__global__ __launch_bounds__(256, 1)
void gemm1_fused(const float* __restrict__ x, const float* __restrict__ bias) {
    extern __shared__ char smem[];
    __nv_bfloat16* sWhi = reinterpret_cast<__nv_bfloat16*>(smem);   // 256 rows
    __nv_bfloat16* sWlo = sWhi + 256 * LDS_STRIDE;
    __nv_bfloat16* sAhi = sWlo + 256 * LDS_STRIDE;                  // 16 rows
    __nv_bfloat16* sAlo = sAhi + 16 * LDS_STRIDE;
    __nv_bfloat16* sGhi = sAlo + 16 * LDS_STRIDE;                   // 16 rows
    __nv_bfloat16* sGlo = sGhi + 16 * LDS_STRIDE;

    const int tid  = threadIdx.x;
    const int wid  = tid >> 5;
    const int lane = tid & 31;
    const int b    = blockIdx.x >> 5;
    const int n0   = (blockIdx.x & 31) * 16;

    copy_plane<256, 256>(g_weHi, sWhi, tid);
    copy_plane<256, 256>(g_weLo, sWlo, tid);

    // ldmatrix addresses
    uint32_t aHiAd, aLoAd, bHiAd[2], bLoAd[2];
    {
        const uint32_t aBH = smem_u32(sAhi), aBL = smem_u32(sAlo);
        const uint32_t bBH = smem_u32(sWhi), bBL = smem_u32(sWlo);
        uint32_t aoff = ((lane & 15) * LDS_STRIDE + (lane >> 4) * 8) * 2;
        aHiAd = aBH + aoff;
        aLoAd = aBL + aoff;
        int bc = ((lane >> 3) & 1) * 8;
#pragma unroll
        for (int p = 0; p < 2; ++p) {
            int br = p * 128 + 16 * wid + ((lane >> 4) << 3) + (lane & 7);
            uint32_t off = (br * LDS_STRIDE + bc) * 2;
            bHiAd[p] = bBH + off;
            bLoAd[p] = bBL + off;
        }
    }

    const int gr = lane >> 2;
    const int gc = (lane & 3) * 2;
    float bp[2][2], bg[2][2];
#pragma unroll
    for (int jj = 0; jj < 2; ++jj) {
        bp[jj][0] = bias[16 * wid + jj * 8 + gc];
        bp[jj][1] = bias[16 * wid + jj * 8 + gc + 1];
        bg[jj][0] = bias[128 + 16 * wid + jj * 8 + gc];
        bg[jj][1] = bias[128 + 16 * wid + jj * 8 + gc + 1];
    }

    // EMA state (gating block, per-lane share of 16x16)
    float s[2][4];
#pragma unroll
    for (int jj = 0; jj < 2; ++jj)
#pragma unroll
        for (int q = 0; q < 4; ++q) s[jj][q] = 0.0f;

    // prefetch t = 0: 16x128 fp32 = 512 float4, 2 per thread
    float4 pf[2];
    {
        size_t rb = ((size_t)(b * Tdim + 0) * Ndim + n0) * 128;
#pragma unroll
        for (int it = 0; it < 2; ++it) {
            int i = tid + it * 256;
            int r = i >> 5, c4 = (i & 31) << 2;
            pf[it] = *reinterpret_cast<const float4*>(x + rb + (size_t)r * 128 + c4);
        }
    }

    for (int t = 0; t < Tdim; ++t) {
        // stage A tile: fp32 -> split bf16 planes
#pragma unroll
        for (int it = 0; it < 2; ++it) {
            int i = tid + it * 256;
            int r = i >> 5, c4 = (i & 31) << 2;
            float4 v = pf[it];
            __nv_bfloat162 h0 = __float22bfloat162_rn(make_float2(v.x, v.y));
            __nv_bfloat162 h1 = __float22bfloat162_rn(make_float2(v.z, v.w));
            float2 h0f = __bfloat1622float2(h0);
            float2 h1f = __bfloat1622float2(h1);
            __nv_bfloat162 l0 = __float22bfloat162_rn(make_float2(v.x - h0f.x, v.y - h0f.y));
            __nv_bfloat162 l1 = __float22bfloat162_rn(make_float2(v.z - h1f.x, v.w - h1f.y));
            int off = r * LDS_STRIDE + c4;
            uint2 hp, lp;
            hp.x = *reinterpret_cast<uint32_t*>(&h0);
            hp.y = *reinterpret_cast<uint32_t*>(&h1);
            lp.x = *reinterpret_cast<uint32_t*>(&l0);
            lp.y = *reinterpret_cast<uint32_t*>(&l1);
            *reinterpret_cast<uint2*>(sAhi + off) = hp;
            *reinterpret_cast<uint2*>(sAlo + off) = lp;
        }
        __syncthreads();

        // prefetch next t (hidden under MMAs)
        if (t + 1 < Tdim) {
            size_t rb = ((size_t)(b * Tdim + t + 1) * Ndim + n0) * 128;
#pragma unroll
            for (int it = 0; it < 2; ++it) {
                int i = tid + it * 256;
                int r = i >> 5, c4 = (i & 31) << 2;
                pf[it] = *reinterpret_cast<const float4*>(x + rb + (size_t)r * 128 + c4);
            }
        }

        float acc[2][2][4];   // [blk: 0=primary 1=gating][n8 jj][q]
#pragma unroll
        for (int p = 0; p < 2; ++p)
#pragma unroll
            for (int jj = 0; jj < 2; ++jj)
#pragma unroll
                for (int q = 0; q < 4; ++q) acc[p][jj][q] = 0.0f;

#pragma unroll
        for (int kk = 0; kk < 8; ++kk) {
            const uint32_t ko = kk * 32;
            uint32_t ah[4], al[4], bh[2][4], bl[2][4];
            LDSM4(ah, aHiAd + ko);
            LDSM4(bh[0], bHiAd[0] + ko);
            LDSM4(bh[1], bHiAd[1] + ko);
            LDSM4(al, aLoAd + ko);
            LDSM4(bl[0], bLoAd[0] + ko);
            LDSM4(bl[1], bLoAd[1] + ko);
#pragma unroll
            for (int p = 0; p < 2; ++p) {
#pragma unroll
                for (int jj = 0; jj < 2; ++jj) {
                    const int wh = jj * 2;
                    float* d = acc[p][jj];
                    MMA16816(d, ah, bh[p][wh], bh[p][wh + 1]);
                    MMA16816(d, ah, bl[p][wh], bl[p][wh + 1]);
                    MMA16816(d, al, bh[p][wh], bh[p][wh + 1]);
                }
            }
        }

        // in-register scan + gate + split, stage to smem for coalesced store
#pragma unroll
        for (int jj = 0; jj < 2; ++jj) {
            float gt[4];
#pragma unroll
            for (int q = 0; q < 4; ++q) {
                float gv = acc[1][jj][q] + bg[jj][q & 1];
                s[jj][q] = fmaf(0.9f, s[jj][q], 0.1f * gv);
                float sig = 1.0f / (1.0f + __expf(-s[jj][q]));
                gt[q] = (acc[0][jj][q] + bp[jj][q & 1]) * sig;
            }
            // pack pairs (q0,q1) row gr, (q2,q3) row gr+8
            const int col = 16 * wid + jj * 8 + gc;
#pragma unroll
            for (int h2 = 0; h2 < 2; ++h2) {
                float2 pr2 = make_float2(gt[h2 * 2], gt[h2 * 2 + 1]);
                __nv_bfloat162 hi2 = __float22bfloat162_rn(pr2);
                float2 hif = __bfloat1622float2(hi2);
                __nv_bfloat162 lo2 = __float22bfloat162_rn(
                    make_float2(pr2.x - hif.x, pr2.y - hif.y));
                int row = gr + h2 * 8;
                *reinterpret_cast<uint32_t*>(sGhi + row * LDS_STRIDE + col) =
                    *reinterpret_cast<uint32_t*>(&hi2);
                *reinterpret_cast<uint32_t*>(sGlo + row * LDS_STRIDE + col) =
                    *reinterpret_cast<uint32_t*>(&lo2);
            }
        }
        __syncthreads();

        // coalesced store of gated planes: 16 rows x 128 bf16 each
        {
            int r = tid >> 4, c8 = (tid & 15) << 3;
            uint4 vh = *reinterpret_cast<const uint4*>(sGhi + r * LDS_STRIDE + c8);
            uint4 vl = *reinterpret_cast<const uint4*>(sGlo + r * LDS_STRIDE + c8);
            size_t g = ((size_t)(b * Tdim + t) * Ndim + n0 + r) * 128 + c8;
            *reinterpret_cast<uint4*>(g_gHi + g) = vh;
            *reinterpret_cast<uint4*>(g_gLo + g) = vl;
        }
    }
}

// ---------------- GEMM2 (persistent, 128-row tiles): out = gated*W_con^T + b ----------------
__global__ __launch_bounds__(512, 1)
void gemm2_p(const float* __restrict__ bias, float* __restrict__ C) {
    extern __shared__ char smem[];
    __nv_bfloat16* sWhi = reinterpret_cast<__nv_bfloat16*>(smem);   // 128 rows
    __nv_bfloat16* sWlo = sWhi + 128 * LDS_STRIDE;
    __nv_bfloat16* sAhi = sWlo + 128 * LDS_STRIDE;                  // 128 rows
    __nv_bfloat16* sAlo = sAhi + 128 * LDS_STRIDE;

    const int tid  = threadIdx.x;
    const int wid  = tid >> 5;
    const int lane = tid & 31;

    copy_plane<128, 512>(g_wcHi, sWhi, tid);
    copy_plane<128, 512>(g_wcLo, sWlo, tid);

    // warp layout: 4m x 4n, each 32x32 of 128x128 tile
    const int m0 = (wid & 3) * 32;
    const int n0 = (wid >> 2) * 32;

    uint32_t aHiAd[2], aLoAd[2], bHiAd[2], bLoAd[2];
    {
        const uint32_t aBH = smem_u32(sAhi), aBL = smem_u32(sAlo);
        const uint32_t bBH = smem_u32(sWhi), bBL = smem_u32(sWlo);
        int ar = m0 + (lane & 15);
        int ac = (lane >> 4) * 8;
#pragma unroll
        for (int i = 0; i < 2; ++i) {
            uint32_t off = ((ar + 16 * i) * LDS_STRIDE + ac) * 2;
            aHiAd[i] = aBH + off;
            aLoAd[i] = aBL + off;
        }
        int br = n0 + ((lane >> 4) << 3) + (lane & 7);
        int bc = ((lane >> 3) & 1) * 8;
#pragma unroll
        for (int j = 0; j < 2; ++j) {
            uint32_t off = ((br + 16 * j) * LDS_STRIDE + bc) * 2;
            bHiAd[j] = bBH + off;
            bLoAd[j] = bBL + off;
        }
    }

    // prefetch tile0: 128x128 bf16 per plane = 2048 uint4, 4/thread/plane
    uint4 pfh[4], pfl[4];
    {
        int t0 = blockIdx.x;
        if (t0 < NT2) {
            const uint4* sh = reinterpret_cast<const uint4*>(g_gHi + (size_t)t0 * 128 * 128);
            const uint4* sl = reinterpret_cast<const uint4*>(g_gLo + (size_t)t0 * 128 * 128);
#pragma unroll
            for (int it = 0; it < 4; ++it) {
                pfh[it] = sh[tid + it * 512];
                pfl[it] = sl[tid + it * 512];
            }
        }
    }

    const int gr = lane >> 2;
    const int gc = (lane & 3) * 2;
    float bv[4][2];
#pragma unroll
    for (int jj = 0; jj < 4; ++jj) {
        bv[jj][0] = bias[n0 + jj * 8 + gc];
        bv[jj][1] = bias[n0 + jj * 8 + gc + 1];
    }

    for (int tile = blockIdx.x; tile < NT2; tile += GRID_P) {
        __syncthreads();
#pragma unroll
        for (int it = 0; it < 4; ++it) {
            int i = tid + it * 512;
            int r = i >> 4, c = (i & 15) << 3;
            *reinterpret_cast<uint4*>(sAhi + r * LDS_STRIDE + c) = pfh[it];
            *reinterpret_cast<uint4*>(sAlo + r * LDS_STRIDE + c) = pfl[it];
        }
        __syncthreads();

        int next = tile + GRID_P;
        if (next < NT2) {
            const uint4* sh = reinterpret_cast<const uint4*>(g_gHi + (size_t)next * 128 * 128);
            const uint4* sl = reinterpret_cast<const uint4*>(g_gLo + (size_t)next * 128 * 128);
#pragma unroll
            for (int it = 0; it < 4; ++it) {
                pfh[it] = sh[tid + it * 512];
                pfl[it] = sl[tid + it * 512];
            }
        }

        float acc[2][4][4];
#pragma unroll
        for (int i = 0; i < 2; ++i)
#pragma unroll
            for (int j = 0; j < 4; ++j)
#pragma unroll
                for (int q = 0; q < 4; ++q) acc[i][j][q] = 0.0f;

#pragma unroll
        for (int kk = 0; kk < 8; ++kk) {
            const uint32_t ko = kk * 32;
            uint32_t ah[2][4], al[2][4], bh[2][4], bl[2][4];
#pragma unroll
            for (int i = 0; i < 2; ++i) { LDSM4(ah[i], aHiAd[i] + ko); }
#pragma unroll
            for (int j = 0; j < 2; ++j) { LDSM4(bh[j], bHiAd[j] + ko); }
#pragma unroll
            for (int i = 0; i < 2; ++i) { LDSM4(al[i], aLoAd[i] + ko); }
#pragma unroll
            for (int j = 0; j < 2; ++j) { LDSM4(bl[j], bLoAd[j] + ko); }
#pragma unroll
            for (int i = 0; i < 2; ++i) {
#pragma unroll
                for (int jj = 0; jj < 4; ++jj) {
                    const int pr = jj >> 1, wh = (jj & 1) * 2;
                    float* d = acc[i][jj];
                    MMA16816(d, ah[i], bh[pr][wh], bh[pr][wh + 1]);
                    MMA16816(d, ah[i], bl[pr][wh], bl[pr][wh + 1]);
                    MMA16816(d, al[i], bh[pr][wh], bh[pr][wh + 1]);
                }
            }
        }

        const int bm0 = tile * 128;
#pragma unroll
        for (int jj = 0; jj < 4; ++jj) {
            const int col = n0 + jj * 8 + gc;
#pragma unroll
            for (int i = 0; i < 2; ++i) {
                const int row = bm0 + m0 + i * 16 + gr;
                float2 o0, o1;
                o0.x = acc[i][jj][0] + bv[jj][0]; o0.y = acc[i][jj][1] + bv[jj][1];
                o1.x = acc[i][jj][2] + bv[jj][0]; o1.y = acc[i][jj][3] + bv[jj][1];
                *reinterpret_cast<float2*>(&C[(size_t)row * 128 + col])       = o0;
                *reinterpret_cast<float2*>(&C[(size_t)(row + 8) * 128 + col]) = o1;
            }
        }
    }
}

// ---------------- launch ----------------
extern "C" void kernel_launch(void* const* d_in, const int* in_sizes, int n_in,
                              void* d_out, int out_size) {
    const float* x     = (const float*)d_in[0];
    const float* W_exp = (const float*)d_in[1];
    const float* b_exp = (const float*)d_in[2];
    const float* W_con = (const float*)d_in[3];
    const float* b_con = (const float*)d_in[4];
    float* out = (float*)d_out;

    constexpr int SMEMF = (2 * 256 + 4 * 16) * LDS_STRIDE * 2;  // 156,672
    constexpr int SMEM2 = 4 * 128 * LDS_STRIDE * 2;             // 139,264
    cudaFuncSetAttribute(gemm1_fused, cudaFuncAttributeMaxDynamicSharedMemorySize, SMEMF);
    cudaFuncSetAttribute(gemm2_p, cudaFuncAttributeMaxDynamicSharedMemorySize, SMEM2);

    split_weights<<<128, 256>>>(W_exp, W_con);

    gemm1_fused<<<Bdim * 32, 256, SMEMF>>>(x, b_exp);

    gemm2_p<<<GRID_P, 512, SMEM2>>>(b_con, out);
}